// round 2
// baseline (speedup 1.0000x reference)
#include <cuda_runtime.h>

// Problem constants
#define NB   8          // batch
#define NC   256        // channels
#define NM   128        // m = C/2
#define NPIX 16384      // N = H*W
#define EPSV 1e-6f

// ---------------- scratch (static device arrays; no allocation) ----------------
__device__ float g_QKV[(size_t)NB * 512 * NPIX];   // rows 0-127 Q, 128-255 K, 256-511 V
__device__ float g_invQ[NB * NPIX];
__device__ float g_invK[NB * NPIX];
__device__ float g_Ksum[NB * NM];
__device__ float g_vsum[NB * NC];
__device__ float g_matrix[NB * NM * NC];           // [b][m][C]
__device__ float g_tailor[NB * NPIX];

// packed dual-fp32 FMA (Blackwell f32x2 pipe; ptxas never emits this from C++)
__device__ __forceinline__ void ffma2(unsigned long long& d,
                                      unsigned long long a,
                                      unsigned long long b) {
    asm("fma.rn.f32x2 %0, %1, %2, %0;" : "+l"(d) : "l"(a), "l"(b));
}
__device__ __forceinline__ float f2lo(unsigned long long v) {
    return __uint_as_float((unsigned)(v & 0xffffffffull));
}
__device__ __forceinline__ float f2hi(unsigned long long v) {
    return __uint_as_float((unsigned)(v >> 32));
}

// ---------------- zero accumulators (graph-replay determinism) ----------------
__global__ void zero_kernel() {
    const int total = NB*NM + NB*NC + NB*NM*NC;
    for (int i = blockIdx.x * blockDim.x + threadIdx.x; i < total;
         i += gridDim.x * blockDim.x) {
        if (i < NB*NM)            g_Ksum[i] = 0.f;
        else if (i < NB*NM+NB*NC) g_vsum[i - NB*NM] = 0.f;
        else                      g_matrix[i - NB*NM - NB*NC] = 0.f;
    }
}

// ---------------- GEMM1: QKV = [Wq;Wk;Wv] @ x + bias ----------------
// grid (NPIX/128, 4, NB), 256 threads, BM=BN=128, BK=16, 8x8 micro-tile (f32x2)
__global__ __launch_bounds__(256) void gemm_qkv(
    const float* __restrict__ x,
    const float* __restrict__ Wq, const float* __restrict__ bq,
    const float* __restrict__ Wk, const float* __restrict__ bk,
    const float* __restrict__ Wv, const float* __restrict__ bv)
{
    const int b  = blockIdx.z;
    const int mt = blockIdx.y;     // 0:Q 1:K 2,3:V halves
    const int nt = blockIdx.x;

    const float *W, *bias; int wrow0;
    if (mt == 0)      { W = Wq; bias = bq; wrow0 = 0; }
    else if (mt == 1) { W = Wk; bias = bk; wrow0 = 0; }
    else              { W = Wv; bias = bv; wrow0 = (mt - 2) * 128; }

    __shared__ float As[16][258];   // [k][2*row] duplicated pairs for LDS.64 A-reads
    __shared__ float Bs[16][128];   // [k][n], ulonglong2 reads

    const int tid = threadIdx.x;
    const int tx = tid & 15, ty = tid >> 4;
    const float* xb = x + (size_t)b * NC * NPIX + (size_t)nt * 128;

    unsigned long long acc[8][4] = {};

    for (int kt = 0; kt < NC / 16; ++kt) {
        #pragma unroll
        for (int s = 0; s < 8; s++) {            // A tile 128x16, duplicated
            int idx = tid + s * 256;
            int r = idx >> 4, k = idx & 15;
            float w = W[(size_t)(wrow0 + r) * NC + kt * 16 + k];
            *reinterpret_cast<float2*>(&As[k][2 * r]) = make_float2(w, w);
        }
        #pragma unroll
        for (int s = 0; s < 8; s++) {            // B tile 16x128
            int idx = tid + s * 256;
            int k = idx >> 7, n = idx & 127;
            Bs[k][n] = xb[(size_t)(kt * 16 + k) * NPIX + n];
        }
        __syncthreads();
        #pragma unroll
        for (int kk = 0; kk < 16; kk++) {
            unsigned long long a[8];
            #pragma unroll
            for (int i = 0; i < 8; i++)
                a[i] = *reinterpret_cast<const unsigned long long*>(
                           &As[kk][2 * (ty * 8 + i)]);
            ulonglong2 b0 = *reinterpret_cast<const ulonglong2*>(&Bs[kk][tx * 8]);
            ulonglong2 b1 = *reinterpret_cast<const ulonglong2*>(&Bs[kk][tx * 8 + 4]);
            unsigned long long bb[4] = {b0.x, b0.y, b1.x, b1.y};
            #pragma unroll
            for (int i = 0; i < 8; i++)
                #pragma unroll
                for (int j = 0; j < 4; j++)
                    ffma2(acc[i][j], a[i], bb[j]);
        }
        __syncthreads();
    }

    float* out = g_QKV + (size_t)b * 512 * NPIX + (size_t)mt * 128 * NPIX
               + (size_t)nt * 128;
    #pragma unroll
    for (int i = 0; i < 8; i++) {
        float bv_ = bias[wrow0 + ty * 8 + i];
        float* orow = out + (size_t)(ty * 8 + i) * NPIX + tx * 8;
        #pragma unroll
        for (int j = 0; j < 4; j++) {
            orow[2 * j]     = f2lo(acc[i][j]) + bv_;
            orow[2 * j + 1] = f2hi(acc[i][j]) + bv_;
        }
    }
}

// ---------------- per-pixel inverse channel norms of Q and K ----------------
__global__ void norms_kernel() {
    const int b = blockIdx.y;
    const int n = blockIdx.x * 256 + threadIdx.x;
    const float* Qb = g_QKV + (size_t)b * 512 * NPIX;
    const float* Kb = Qb + (size_t)128 * NPIX;
    float sq = 0.f, sk = 0.f;
    for (int c = 0; c < NM; c++) {
        float q = Qb[(size_t)c * NPIX + n]; sq = fmaf(q, q, sq);
        float k = Kb[(size_t)c * NPIX + n]; sk = fmaf(k, k, sk);
    }
    g_invQ[b * NPIX + n] = rsqrtf(sq);
    g_invK[b * NPIX + n] = rsqrtf(sk);
}

// ---------------- GEMM2: matrix[m][C] = sum_n Kn[m,n] V[C,n]; + Ksum, vsum ----
// grid (16 splitK, 2 C-halves, NB), 256 thr. Each block reduces 1024 pixels.
__global__ __launch_bounds__(256) void gemm_kv() {
    const int chunk = blockIdx.x, ch = blockIdx.y, b = blockIdx.z;

    __shared__ float Ks[16][264];   // [nloc][2*m] duplicated pairs (A role)
    __shared__ float Vs[16][132];   // [nloc][C-ch] (B role), ulonglong2 reads
    __shared__ float red[128];

    const int tid = threadIdx.x, tx = tid & 15, ty = tid >> 4;
    const float* Kb = g_QKV + (size_t)b * 512 * NPIX + (size_t)128 * NPIX;
    const float* Vb = g_QKV + (size_t)b * 512 * NPIX + (size_t)256 * NPIX
                    + (size_t)ch * 128 * NPIX;
    const float* iK = g_invK + b * NPIX;
    const int n0 = chunk * 1024;

    unsigned long long acc[8][4] = {};
    float ksacc[8] = {}, vsacc[8] = {};
    const int nl = tid & 15;

    for (int it = 0; it < 64; ++it) {
        const int nb_ = n0 + it * 16;
        const float ik = iK[nb_ + nl];
        #pragma unroll
        for (int s = 0; s < 8; s++) {
            int idx = tid + s * 256;
            int c = idx >> 4;                 // = 16*s + ty
            float kv = Kb[(size_t)c * NPIX + nb_ + nl] * ik;
            *reinterpret_cast<float2*>(&Ks[nl][2 * c]) = make_float2(kv, kv);
            ksacc[s] += kv;
            float vv = Vb[(size_t)c * NPIX + nb_ + nl];
            Vs[nl][c] = vv;  vsacc[s] += vv;
        }
        __syncthreads();
        #pragma unroll
        for (int kk = 0; kk < 16; kk++) {
            unsigned long long a[8];
            #pragma unroll
            for (int i = 0; i < 8; i++)
                a[i] = *reinterpret_cast<const unsigned long long*>(
                           &Ks[kk][2 * (ty * 8 + i)]);
            ulonglong2 b0 = *reinterpret_cast<const ulonglong2*>(&Vs[kk][tx * 8]);
            ulonglong2 b1 = *reinterpret_cast<const ulonglong2*>(&Vs[kk][tx * 8 + 4]);
            unsigned long long bb[4] = {b0.x, b0.y, b1.x, b1.y};
            #pragma unroll
            for (int i = 0; i < 8; i++)
                #pragma unroll
                for (int j = 0; j < 4; j++)
                    ffma2(acc[i][j], a[i], bb[j]);
        }
        __syncthreads();
    }

    // matrix partial -> global atomics
    float* mb = g_matrix + (size_t)b * NM * NC + ch * 128;
    #pragma unroll
    for (int i = 0; i < 8; i++)
        #pragma unroll
        for (int j = 0; j < 4; j++) {
            atomicAdd(&mb[(size_t)(ty * 8 + i) * NC + tx * 8 + 2 * j],
                      f2lo(acc[i][j]));
            atomicAdd(&mb[(size_t)(ty * 8 + i) * NC + tx * 8 + 2 * j + 1],
                      f2hi(acc[i][j]));
        }

    // vsum (this block's C half)
    if (tid < 128) red[tid] = 0.f;
    __syncthreads();
    #pragma unroll
    for (int s = 0; s < 8; s++) atomicAdd(&red[ty + s * 16], vsacc[s]);
    __syncthreads();
    if (tid < 128) atomicAdd(&g_vsum[b * NC + ch * 128 + tid], red[tid]);
    __syncthreads();

    // Ksum (only C-half 0 blocks, K is shared between halves)
    if (ch == 0) {
        if (tid < 128) red[tid] = 0.f;
        __syncthreads();
        #pragma unroll
        for (int s = 0; s < 8; s++) atomicAdd(&red[ty + s * 16], ksacc[s]);
        __syncthreads();
        if (tid < 128) atomicAdd(&g_Ksum[b * NM + tid], red[tid]);
    }
}

// ---------------- tailor[n] = 1/(N + Qn . (Ksum + eps)) ----------------
__global__ void tailor_kernel() {
    __shared__ float ks[128];
    const int b = blockIdx.y;
    const int n = blockIdx.x * 256 + threadIdx.x;
    if (threadIdx.x < 128) ks[threadIdx.x] = g_Ksum[b * NM + threadIdx.x] + EPSV;
    __syncthreads();
    const float* Qb = g_QKV + (size_t)b * 512 * NPIX;
    float dot = 0.f;
    for (int c = 0; c < NM; c++)
        dot = fmaf(Qb[(size_t)c * NPIX + n], ks[c], dot);
    g_tailor[b * NPIX + n] =
        1.0f / ((float)NPIX + g_invQ[b * NPIX + n] * dot);
}

// ---------------- GEMM3: out[c,n] = g*tailor[n]*(vsum[c] + sum_m matrix[m][c]*Qn[m,n]) --
// grid (NPIX/128, 2, NB), 256 thr, K = 128 (m), BK=16 (f32x2)
__global__ __launch_bounds__(256) void gemm_out(
    const float* __restrict__ gamma, float* __restrict__ out)
{
    const int nt = blockIdx.x, ch = blockIdx.y, b = blockIdx.z;

    __shared__ float As[16][258];   // [mloc][2*c] duplicated pairs
    __shared__ float Bs[16][128];   // [mloc][n]

    const int tid = threadIdx.x, tx = tid & 15, ty = tid >> 4;
    const float* Qb  = g_QKV + (size_t)b * 512 * NPIX + (size_t)nt * 128;
    const float* iQ  = g_invQ + b * NPIX + nt * 128;
    const float* mat = g_matrix + (size_t)b * NM * NC + ch * 128;

    unsigned long long acc[8][4] = {};

    for (int mt = 0; mt < 8; ++mt) {
        #pragma unroll
        for (int s = 0; s < 8; s++) {
            int idx = tid + s * 256;
            int ml = idx >> 7, c = idx & 127;
            float w = mat[(size_t)(mt * 16 + ml) * NC + c];
            *reinterpret_cast<float2*>(&As[ml][2 * c]) = make_float2(w, w);
            Bs[ml][c] = Qb[(size_t)(mt * 16 + ml) * NPIX + c] * iQ[c];
        }
        __syncthreads();
        #pragma unroll
        for (int kk = 0; kk < 16; kk++) {
            unsigned long long a[8];
            #pragma unroll
            for (int i = 0; i < 8; i++)
                a[i] = *reinterpret_cast<const unsigned long long*>(
                           &As[kk][2 * (ty * 8 + i)]);
            ulonglong2 b0 = *reinterpret_cast<const ulonglong2*>(&Bs[kk][tx * 8]);
            ulonglong2 b1 = *reinterpret_cast<const ulonglong2*>(&Bs[kk][tx * 8 + 4]);
            unsigned long long bb[4] = {b0.x, b0.y, b1.x, b1.y};
            #pragma unroll
            for (int i = 0; i < 8; i++)
                #pragma unroll
                for (int j = 0; j < 4; j++)
                    ffma2(acc[i][j], a[i], bb[j]);
        }
        __syncthreads();
    }

    const float g = gamma[0];
    float tl[8];
    #pragma unroll
    for (int j = 0; j < 8; j++)
        tl[j] = g * g_tailor[b * NPIX + nt * 128 + tx * 8 + j];

    float* ob = out + (size_t)b * NC * NPIX + (size_t)ch * 128 * NPIX
              + (size_t)nt * 128;
    #pragma unroll
    for (int i = 0; i < 8; i++) {
        float vs = g_vsum[b * NC + ch * 128 + ty * 8 + i];
        float* orow = ob + (size_t)(ty * 8 + i) * NPIX + tx * 8;
        #pragma unroll
        for (int j = 0; j < 4; j++) {
            orow[2 * j]     = tl[2 * j]     * (vs + f2lo(acc[i][j]));
            orow[2 * j + 1] = tl[2 * j + 1] * (vs + f2hi(acc[i][j]));
        }
    }
}

// ---------------- launch ----------------
extern "C" void kernel_launch(void* const* d_in, const int* in_sizes, int n_in,
                              void* d_out, int out_size)
{
    const float* x     = (const float*)d_in[0];
    const float* Wq    = (const float*)d_in[1];
    const float* bq    = (const float*)d_in[2];
    const float* Wk    = (const float*)d_in[3];
    const float* bk    = (const float*)d_in[4];
    const float* Wv    = (const float*)d_in[5];
    const float* bv    = (const float*)d_in[6];
    const float* gamma = (const float*)d_in[7];
    float* out = (float*)d_out;

    zero_kernel<<<64, 256>>>();
    gemm_qkv<<<dim3(NPIX / 128, 4, NB), 256>>>(x, Wq, bq, Wk, bk, Wv, bv);
    norms_kernel<<<dim3(NPIX / 256, NB), 256>>>();
    gemm_kv<<<dim3(16, 2, NB), 256>>>();
    tailor_kernel<<<dim3(NPIX / 256, NB), 256>>>();
    gemm_out<<<dim3(NPIX / 128, 2, NB), 256>>>(gamma, out);
}

// round 3
// speedup vs baseline: 2.8636x; 2.8636x over previous
#include <cuda_runtime.h>

// Problem constants
#define NB   8          // batch
#define NC   256        // channels
#define NM   128        // m = C/2
#define NPIX 16384      // N = H*W
#define EPSV 1e-6f

// ---------------- scratch (static device arrays; no allocation) ----------------
__device__ float g_QKV[(size_t)NB * 512 * NPIX];   // rows 0-127 Q, 128-255 K, 256-511 V
__device__ float g_invQ[NB * NPIX];
__device__ float g_invK[NB * NPIX];
__device__ float g_Ksum[NB * NM];
__device__ float g_vsum[NB * NC];
__device__ float g_matrix[NB * NM * NC];           // [b][m][C]
__device__ float g_tailor[NB * NPIX];

// ---------------- tf32 helpers ----------------
__device__ __forceinline__ float tf32r(float f) {
    unsigned u;
    asm("cvt.rna.tf32.f32 %0, %1;" : "=r"(u) : "f"(f));
    return __uint_as_float(u);
}
__device__ __forceinline__ void mma_tf32(float* d, const unsigned* a,
                                         const unsigned* b) {
    asm volatile(
        "mma.sync.aligned.m16n8k8.row.col.f32.tf32.tf32.f32 "
        "{%0,%1,%2,%3}, {%4,%5,%6,%7}, {%8,%9}, {%0,%1,%2,%3};"
        : "+f"(d[0]), "+f"(d[1]), "+f"(d[2]), "+f"(d[3])
        : "r"(a[0]), "r"(a[1]), "r"(a[2]), "r"(a[3]), "r"(b[0]), "r"(b[1]));
}

#define SMS 132   // smem row stride (128 + 4): stride mod 32 == 4 -> conflict-free frags

// ---------------- zero accumulators (graph-replay determinism) ----------------
__global__ void zero_kernel() {
    const int total = NB*NM + NB*NC + NB*NM*NC;
    for (int i = blockIdx.x * blockDim.x + threadIdx.x; i < total;
         i += gridDim.x * blockDim.x) {
        if (i < NB*NM)            g_Ksum[i] = 0.f;
        else if (i < NB*NM+NB*NC) g_vsum[i - NB*NM] = 0.f;
        else                      g_matrix[i - NB*NM - NB*NC] = 0.f;
    }
}

// compute 16 MMAs for one BK=32 smem stage (4 ksteps), warp tile 32x64
__device__ __forceinline__ void mma_stage(const float (*As)[SMS],
                                          const float (*Bs)[SMS],
                                          float acc[2][8][4],
                                          int warp_m, int warp_n, int lane) {
    const int lq = lane & 3, lr = lane >> 2;
    #pragma unroll
    for (int kk = 0; kk < 4; kk++) {
        const int k0 = kk * 8 + lq;
        unsigned afr[2][4], bfr[8][2];
        #pragma unroll
        for (int i = 0; i < 2; i++) {
            int mr = warp_m * 32 + i * 16 + lr;
            afr[i][0] = __float_as_uint(As[k0][mr]);
            afr[i][1] = __float_as_uint(As[k0][mr + 8]);
            afr[i][2] = __float_as_uint(As[k0 + 4][mr]);
            afr[i][3] = __float_as_uint(As[k0 + 4][mr + 8]);
        }
        #pragma unroll
        for (int j = 0; j < 8; j++) {
            int nc = warp_n * 64 + j * 8 + lr;
            bfr[j][0] = __float_as_uint(Bs[k0][nc]);
            bfr[j][1] = __float_as_uint(Bs[k0 + 4][nc]);
        }
        #pragma unroll
        for (int i = 0; i < 2; i++)
            #pragma unroll
            for (int j = 0; j < 8; j++)
                mma_tf32(acc[i][j], afr[i], bfr[j]);
    }
}

// ---------------- GEMM1: QKV = [Wq;Wk;Wv] @ x + bias (tf32 tensor) ----------------
// grid (NPIX/128, 4, NB), 256 thr
__global__ __launch_bounds__(256) void gemm_qkv(
    const float* __restrict__ x,
    const float* __restrict__ Wq, const float* __restrict__ bq,
    const float* __restrict__ Wk, const float* __restrict__ bk,
    const float* __restrict__ Wv, const float* __restrict__ bv)
{
    const int b  = blockIdx.z;
    const int mt = blockIdx.y;     // 0:Q 1:K 2,3:V halves
    const int nblk = blockIdx.x;

    const float *W, *bias; int wrow0;
    if (mt == 0)      { W = Wq; bias = bq; wrow0 = 0; }
    else if (mt == 1) { W = Wk; bias = bk; wrow0 = 0; }
    else              { W = Wv; bias = bv; wrow0 = (mt - 2) * 128; }

    __shared__ float As[32][SMS];   // [k][m]
    __shared__ float Bs[32][SMS];   // [k][n]

    const int tid = threadIdx.x, lane = tid & 31, wid = tid >> 5;
    const int warp_m = wid & 3, warp_n = wid >> 2;
    const int n0 = nblk * 128;
    const float* xb = x + (size_t)b * NC * NPIX;

    // load indices
    const int aq = (tid & 7) * 4, am = tid >> 3;          // A: k-quad, m-row
    const int bn = (tid & 31) * 4, bkr = tid >> 5;        // B: n-quad, k-row

    float acc[2][8][4] = {};
    float4 pa[4], pb[4];

    // prefetch iter 0
    #pragma unroll
    for (int s = 0; s < 4; s++) {
        pa[s] = *reinterpret_cast<const float4*>(
            &W[(size_t)(wrow0 + am + 32 * s) * NC + aq]);
        pb[s] = *reinterpret_cast<const float4*>(
            &xb[(size_t)(bkr + 8 * s) * NPIX + n0 + bn]);
    }

    for (int it = 0; it < 8; ++it) {
        #pragma unroll
        for (int s = 0; s < 4; s++) {
            As[aq + 0][am + 32 * s] = tf32r(pa[s].x);
            As[aq + 1][am + 32 * s] = tf32r(pa[s].y);
            As[aq + 2][am + 32 * s] = tf32r(pa[s].z);
            As[aq + 3][am + 32 * s] = tf32r(pa[s].w);
            float4 v = pb[s];
            v.x = tf32r(v.x); v.y = tf32r(v.y); v.z = tf32r(v.z); v.w = tf32r(v.w);
            *reinterpret_cast<float4*>(&Bs[bkr + 8 * s][bn]) = v;
        }
        __syncthreads();
        if (it + 1 < 8) {
            const int kt = (it + 1) * 32;
            #pragma unroll
            for (int s = 0; s < 4; s++) {
                pa[s] = *reinterpret_cast<const float4*>(
                    &W[(size_t)(wrow0 + am + 32 * s) * NC + kt + aq]);
                pb[s] = *reinterpret_cast<const float4*>(
                    &xb[(size_t)(kt + bkr + 8 * s) * NPIX + n0 + bn]);
            }
        }
        mma_stage(As, Bs, acc, warp_m, warp_n, lane);
        __syncthreads();
    }

    // epilogue: bias, store
    float* out = g_QKV + ((size_t)b * 512 + (size_t)mt * 128) * NPIX;
    const int lq = lane & 3, lr = lane >> 2;
    #pragma unroll
    for (int i = 0; i < 2; i++) {
        int r0 = warp_m * 32 + i * 16 + lr;
        float b0 = bias[wrow0 + r0], b1 = bias[wrow0 + r0 + 8];
        #pragma unroll
        for (int j = 0; j < 8; j++) {
            int ncol = n0 + warp_n * 64 + j * 8 + 2 * lq;
            *reinterpret_cast<float2*>(&out[(size_t)r0 * NPIX + ncol]) =
                make_float2(acc[i][j][0] + b0, acc[i][j][1] + b0);
            *reinterpret_cast<float2*>(&out[(size_t)(r0 + 8) * NPIX + ncol]) =
                make_float2(acc[i][j][2] + b1, acc[i][j][3] + b1);
        }
    }
}

// ---------------- per-pixel inverse channel norms of Q and K ----------------
__global__ void norms_kernel() {
    const int b = blockIdx.y;
    const int n = blockIdx.x * 256 + threadIdx.x;
    const float* Qb = g_QKV + (size_t)b * 512 * NPIX;
    const float* Kb = Qb + (size_t)128 * NPIX;
    float sq = 0.f, sk = 0.f;
    for (int c = 0; c < NM; c++) {
        float q = Qb[(size_t)c * NPIX + n]; sq = fmaf(q, q, sq);
        float k = Kb[(size_t)c * NPIX + n]; sk = fmaf(k, k, sk);
    }
    g_invQ[b * NPIX + n] = rsqrtf(sq);
    g_invK[b * NPIX + n] = rsqrtf(sk);
}

// ---------------- GEMM2: matrix[m][C] += Kn @ V^T over pixel chunks + Ksum/vsum --
// grid (16 chunks, 2 ch, NB), 256 thr, each block reduces 1024 pixels
__global__ __launch_bounds__(256) void gemm_kv() {
    const int chunk = blockIdx.x, ch = blockIdx.y, b = blockIdx.z;

    __shared__ float As[32][SMS];   // [npix_loc][m]  (Kn, A role: row=m, k=n)
    __shared__ float Bs[32][SMS];   // [npix_loc][c]  (V^T, B role)
    __shared__ float redm[128], redc[128];

    const int tid = threadIdx.x, lane = tid & 31, wid = tid >> 5;
    const int warp_m = wid & 3, warp_n = wid >> 2;

    const float* Kb = g_QKV + ((size_t)b * 512 + 128) * NPIX;
    const float* Vb = g_QKV + ((size_t)b * 512 + 256 + (size_t)ch * 128) * NPIX;
    const float* iK = g_invK + b * NPIX;
    const int n0 = chunk * 1024;

    const int aq = (tid & 7) * 4, am = tid >> 3;     // A: n-quad, m-row (0..31)
    const int vc = tid & 127, vg = (tid >> 7) * 16;  // B: c, n-halfgroup

    float acc[2][8][4] = {};
    float ksacc[4] = {}, vsacc = 0.f;
    float4 pa[4], pik, pb[4];

    // prefetch iter 0
    pik = *reinterpret_cast<const float4*>(&iK[n0 + aq]);
    #pragma unroll
    for (int s = 0; s < 4; s++) {
        pa[s] = *reinterpret_cast<const float4*>(
            &Kb[(size_t)(am + 32 * s) * NPIX + n0 + aq]);
        pb[s] = *reinterpret_cast<const float4*>(
            &Vb[(size_t)vc * NPIX + n0 + vg + 4 * s]);
    }

    for (int it = 0; it < 32; ++it) {
        #pragma unroll
        for (int s = 0; s < 4; s++) {
            float4 k4 = pa[s];
            k4.x *= pik.x; k4.y *= pik.y; k4.z *= pik.z; k4.w *= pik.w;
            ksacc[s] += k4.x + k4.y + k4.z + k4.w;
            As[aq + 0][am + 32 * s] = tf32r(k4.x);
            As[aq + 1][am + 32 * s] = tf32r(k4.y);
            As[aq + 2][am + 32 * s] = tf32r(k4.z);
            As[aq + 3][am + 32 * s] = tf32r(k4.w);
            float4 v4 = pb[s];
            vsacc += v4.x + v4.y + v4.z + v4.w;
            Bs[vg + 4 * s + 0][vc] = tf32r(v4.x);
            Bs[vg + 4 * s + 1][vc] = tf32r(v4.y);
            Bs[vg + 4 * s + 2][vc] = tf32r(v4.z);
            Bs[vg + 4 * s + 3][vc] = tf32r(v4.w);
        }
        __syncthreads();
        if (it + 1 < 32) {
            const int nb_ = n0 + (it + 1) * 32;
            pik = *reinterpret_cast<const float4*>(&iK[nb_ + aq]);
            #pragma unroll
            for (int s = 0; s < 4; s++) {
                pa[s] = *reinterpret_cast<const float4*>(
                    &Kb[(size_t)(am + 32 * s) * NPIX + nb_ + aq]);
                pb[s] = *reinterpret_cast<const float4*>(
                    &Vb[(size_t)vc * NPIX + nb_ + vg + 4 * s]);
            }
        }
        mma_stage(As, Bs, acc, warp_m, warp_n, lane);
        __syncthreads();
    }

    // matrix partials -> global atomics
    float* mb = g_matrix + (size_t)b * NM * NC + ch * 128;
    const int lq = lane & 3, lr = lane >> 2;
    #pragma unroll
    for (int i = 0; i < 2; i++) {
        int r0 = warp_m * 32 + i * 16 + lr;
        #pragma unroll
        for (int j = 0; j < 8; j++) {
            int col = warp_n * 64 + j * 8 + 2 * lq;
            atomicAdd(&mb[(size_t)r0 * NC + col],       acc[i][j][0]);
            atomicAdd(&mb[(size_t)r0 * NC + col + 1],   acc[i][j][1]);
            atomicAdd(&mb[(size_t)(r0+8) * NC + col],   acc[i][j][2]);
            atomicAdd(&mb[(size_t)(r0+8) * NC + col+1], acc[i][j][3]);
        }
    }

    // Ksum / vsum reductions
    if (tid < 128) { redm[tid] = 0.f; redc[tid] = 0.f; }
    __syncthreads();
    #pragma unroll
    for (int s = 0; s < 4; s++) atomicAdd(&redm[am + 32 * s], ksacc[s]);
    atomicAdd(&redc[vc], vsacc);
    __syncthreads();
    if (tid < 128) {
        atomicAdd(&g_vsum[b * NC + ch * 128 + tid], redc[tid]);
        if (ch == 0) atomicAdd(&g_Ksum[b * NM + tid], redm[tid]);
    }
}

// ---------------- tailor[n] = 1/(N + Qn . (Ksum + eps)) ----------------
__global__ void tailor_kernel() {
    __shared__ float ks[128];
    const int b = blockIdx.y;
    const int n = blockIdx.x * 256 + threadIdx.x;
    if (threadIdx.x < 128) ks[threadIdx.x] = g_Ksum[b * NM + threadIdx.x] + EPSV;
    __syncthreads();
    const float* Qb = g_QKV + (size_t)b * 512 * NPIX;
    float dot = 0.f;
    for (int c = 0; c < NM; c++)
        dot = fmaf(Qb[(size_t)c * NPIX + n], ks[c], dot);
    g_tailor[b * NPIX + n] =
        1.0f / ((float)NPIX + g_invQ[b * NPIX + n] * dot);
}

// ---------------- GEMM3: out[c,n] = g*tailor[n]*(vsum[c] + matrix^T @ Qn) ----------
// grid (NPIX/128, 2, NB), 256 thr, K = 128
__global__ __launch_bounds__(256) void gemm_out(
    const float* __restrict__ gamma, float* __restrict__ out)
{
    const int nblk = blockIdx.x, ch = blockIdx.y, b = blockIdx.z;

    __shared__ float As[32][SMS];   // [m_loc][c]
    __shared__ float Bs[32][SMS];   // [m_loc][n]
    __shared__ float stl[128], svs[128];

    const int tid = threadIdx.x, lane = tid & 31, wid = tid >> 5;
    const int warp_m = wid & 3, warp_n = wid >> 2;
    const int n0 = nblk * 128;

    const float* Qb  = g_QKV + (size_t)b * 512 * NPIX;
    const float* iQ  = g_invQ + b * NPIX;
    const float* mat = g_matrix + (size_t)b * NM * NC + ch * 128;

    const int acq = (tid & 31) * 4, amr = tid >> 5;   // A: c-quad, m-row (0..7)
    const int bn4 = (tid & 31) * 4, bmr = tid >> 5;   // B: n-quad, m-row

    if (tid < 128) {
        stl[tid] = gamma[0] * g_tailor[b * NPIX + n0 + tid];
        svs[tid] = g_vsum[b * NC + ch * 128 + tid];
    }

    float4 piq = *reinterpret_cast<const float4*>(&iQ[n0 + bn4]);
    float acc[2][8][4] = {};
    float4 pa[4], pb[4];

    #pragma unroll
    for (int s = 0; s < 4; s++) {
        pa[s] = *reinterpret_cast<const float4*>(
            &mat[(size_t)(amr + 8 * s) * NC + acq]);
        pb[s] = *reinterpret_cast<const float4*>(
            &Qb[(size_t)(bmr + 8 * s) * NPIX + n0 + bn4]);
    }

    for (int it = 0; it < 4; ++it) {
        #pragma unroll
        for (int s = 0; s < 4; s++) {
            float4 a4 = pa[s];
            a4.x = tf32r(a4.x); a4.y = tf32r(a4.y);
            a4.z = tf32r(a4.z); a4.w = tf32r(a4.w);
            *reinterpret_cast<float4*>(&As[amr + 8 * s][acq]) = a4;
            float4 q4 = pb[s];
            q4.x = tf32r(q4.x * piq.x); q4.y = tf32r(q4.y * piq.y);
            q4.z = tf32r(q4.z * piq.z); q4.w = tf32r(q4.w * piq.w);
            *reinterpret_cast<float4*>(&Bs[bmr + 8 * s][bn4]) = q4;
        }
        __syncthreads();
        if (it + 1 < 4) {
            const int m0 = (it + 1) * 32;
            #pragma unroll
            for (int s = 0; s < 4; s++) {
                pa[s] = *reinterpret_cast<const float4*>(
                    &mat[(size_t)(m0 + amr + 8 * s) * NC + acq]);
                pb[s] = *reinterpret_cast<const float4*>(
                    &Qb[(size_t)(m0 + bmr + 8 * s) * NPIX + n0 + bn4]);
            }
        }
        mma_stage(As, Bs, acc, warp_m, warp_n, lane);
        __syncthreads();
    }

    float* ob = out + ((size_t)b * NC + (size_t)ch * 128) * NPIX;
    const int lq = lane & 3, lr = lane >> 2;
    #pragma unroll
    for (int i = 0; i < 2; i++) {
        int r0 = warp_m * 32 + i * 16 + lr;
        float v0 = svs[r0], v1 = svs[r0 + 8];
        #pragma unroll
        for (int j = 0; j < 8; j++) {
            int ncl = warp_n * 64 + j * 8 + 2 * lq;
            float t0 = stl[ncl], t1 = stl[ncl + 1];
            *reinterpret_cast<float2*>(&ob[(size_t)r0 * NPIX + n0 + ncl]) =
                make_float2(t0 * (v0 + acc[i][j][0]), t1 * (v0 + acc[i][j][1]));
            *reinterpret_cast<float2*>(&ob[(size_t)(r0 + 8) * NPIX + n0 + ncl]) =
                make_float2(t0 * (v1 + acc[i][j][2]), t1 * (v1 + acc[i][j][3]));
        }
    }
}

// ---------------- launch ----------------
extern "C" void kernel_launch(void* const* d_in, const int* in_sizes, int n_in,
                              void* d_out, int out_size)
{
    const float* x     = (const float*)d_in[0];
    const float* Wq    = (const float*)d_in[1];
    const float* bq    = (const float*)d_in[2];
    const float* Wk    = (const float*)d_in[3];
    const float* bk    = (const float*)d_in[4];
    const float* Wv    = (const float*)d_in[5];
    const float* bv    = (const float*)d_in[6];
    const float* gamma = (const float*)d_in[7];
    float* out = (float*)d_out;

    zero_kernel<<<64, 256>>>();
    gemm_qkv<<<dim3(NPIX / 128, 4, NB), 256>>>(x, Wq, bq, Wk, bk, Wv, bv);
    norms_kernel<<<dim3(NPIX / 256, NB), 256>>>();
    gemm_kv<<<dim3(16, 2, NB), 256>>>();
    tailor_kernel<<<dim3(NPIX / 256, NB), 256>>>();
    gemm_out<<<dim3(NPIX / 128, 2, NB), 256>>>(gamma, out);
}